// round 1
// baseline (speedup 1.0000x reference)
#include <cuda_runtime.h>
#include <cuda_bf16.h>
#include <math.h>

// CBTree: B=4, L=9, d=256.
// offsets[l] = (4^l - 1)/3 ; leaves at offsets[8] = 21845, 65536 rows.
// Per level l (7..0):
//   u[p, 0:256]   = 1*h[4p] + (2/3)*h[4p+1] + (1/3)*h[4p+2]
//   u[p, 256:512] = (1/3)*h[4p+1] + (2/3)*h[4p+2] + 1*h[4p+3]
//   h_out[p, j] = tanh( sum_k u[p,k]*WT[k,j] + vectors[off_l + p, j] )
// where WT (512 x 256) row-major: WT[k][j] = (k<256) ? Wl[j][k] : Wr[j][k-256].

#define D 256
#define K2 512

// ---------------- scratch (static device allocations) ----------------
__device__ float g_bufA[16384 * 256];   // 16 MB
__device__ float g_bufB[16384 * 256];   // 16 MB
__device__ float g_u[16384 * 512];      // 32 MB
__device__ float g_WT[512 * 256];       // 0.5 MB

// ---------------- prep: build WT = [Wl^T ; Wr^T] (K x N) ----------------
__global__ void prep_wt_kernel(const float* __restrict__ Wl,
                               const float* __restrict__ Wr,
                               float* __restrict__ WT) {
    int idx = blockIdx.x * blockDim.x + threadIdx.x;   // 512*256 = 131072
    if (idx >= K2 * D) return;
    int k = idx >> 8;
    int j = idx & 255;
    WT[idx] = (k < D) ? Wl[j * D + k] : Wr[j * D + (k - D)];
}

// ---------------- child reduction: h (4*n_par x 256) -> u (n_par x 512) ----------------
__global__ void reduce_kernel(const float* __restrict__ h,
                              float* __restrict__ u,
                              int n_par) {
    int idx = blockIdx.x * blockDim.x + threadIdx.x;   // float4 units of u
    int total = n_par * 128;                           // 512 floats / 4
    if (idx >= total) return;
    int p = idx >> 7;
    int q = idx & 127;
    const float4* hp = (const float4*)(h + (size_t)p * 1024);  // 4 rows x 64 float4
    float4 r;
    if (q < 64) {
        // left: lc = [1, 2/3, 1/3, 0]
        float4 a = hp[q];
        float4 b = hp[64 + q];
        float4 c = hp[128 + q];
        const float c1 = 2.0f / 3.0f, c2 = 1.0f / 3.0f;
        r.x = a.x + c1 * b.x + c2 * c.x;
        r.y = a.y + c1 * b.y + c2 * c.y;
        r.z = a.z + c1 * b.z + c2 * c.z;
        r.w = a.w + c1 * b.w + c2 * c.w;
    } else {
        // right: rc = [0, 1/3, 2/3, 1]
        int q2 = q - 64;
        float4 b = hp[64 + q2];
        float4 c = hp[128 + q2];
        float4 d = hp[192 + q2];
        const float c1 = 1.0f / 3.0f, c2 = 2.0f / 3.0f;
        r.x = c1 * b.x + c2 * c.x + d.x;
        r.y = c1 * b.y + c2 * c.y + d.y;
        r.z = c1 * b.z + c2 * c.z + d.z;
        r.w = c1 * b.w + c2 * c.w + d.w;
    }
    ((float4*)u)[idx] = r;
}

// ---------------- fused GEMM + bias + tanh ----------------
// C[p, j] = tanh( A[p, :] . WT[:, j] + bias[p, j] )
// A: M x 512, WT: 512 x 256 (K x N row-major), bias/C: M x 256
#define BM 64
#define BN 128
#define BK 16
#define TM 8
#define TN 8
// threads = (BM/TM) * (BN/TN) = 8 * 16 = 128

__global__ void __launch_bounds__(128)
gemm_tanh_kernel(const float* __restrict__ A,
                 const float* __restrict__ B,
                 const float* __restrict__ bias,
                 float* __restrict__ C,
                 int M) {
    __shared__ float As[BK][BM + 4];   // row stride 68 floats = 272B (16B-aligned)
    __shared__ float Bs[BK][BN];

    const int bm = blockIdx.y * BM;
    const int bn = blockIdx.x * BN;
    const int tid = threadIdx.x;
    const int trow = tid >> 4;   // 0..7  -> rows [trow*8, trow*8+8)
    const int tcol = tid & 15;   // 0..15 -> cols [tcol*8, tcol*8+8)

    float acc[TM][TN];
#pragma unroll
    for (int i = 0; i < TM; i++)
#pragma unroll
        for (int j = 0; j < TN; j++) acc[i][j] = 0.0f;

    for (int k0 = 0; k0 < K2; k0 += BK) {
        // --- stage global loads into registers ---
        float4 areg[2];
#pragma unroll
        for (int i = 0; i < 2; i++) {
            int e = i * 128 + tid;          // 0..255
            int m = e >> 2;                 // 0..63
            int kq = e & 3;                 // float4 within the BK slice
            int grow = bm + m;
            if (grow < M)
                areg[i] = *(const float4*)(A + (size_t)grow * K2 + k0 + kq * 4);
            else
                areg[i] = make_float4(0.f, 0.f, 0.f, 0.f);
        }
        float4 breg[4];
#pragma unroll
        for (int i = 0; i < 4; i++) {
            int e = i * 128 + tid;          // 0..511
            int kr = e >> 5;                // 0..15
            int n4 = e & 31;
            breg[i] = *(const float4*)(B + (size_t)(k0 + kr) * D + bn + n4 * 4);
        }

        __syncthreads();   // previous iteration's compute done reading smem

        // --- store to shared ---
#pragma unroll
        for (int i = 0; i < 2; i++) {
            int e = i * 128 + tid;
            int m = e >> 2;
            int kq = e & 3;
            As[kq * 4 + 0][m] = areg[i].x;
            As[kq * 4 + 1][m] = areg[i].y;
            As[kq * 4 + 2][m] = areg[i].z;
            As[kq * 4 + 3][m] = areg[i].w;
        }
#pragma unroll
        for (int i = 0; i < 4; i++) {
            int e = i * 128 + tid;
            int kr = e >> 5;
            int n4 = e & 31;
            *(float4*)(&Bs[kr][n4 * 4]) = breg[i];
        }

        __syncthreads();

        // --- compute ---
#pragma unroll
        for (int kk = 0; kk < BK; kk++) {
            float a[TM], b[TN];
            *(float4*)(a)     = *(const float4*)(&As[kk][trow * TM]);
            *(float4*)(a + 4) = *(const float4*)(&As[kk][trow * TM + 4]);
            *(float4*)(b)     = *(const float4*)(&Bs[kk][tcol * TN]);
            *(float4*)(b + 4) = *(const float4*)(&Bs[kk][tcol * TN + 4]);
#pragma unroll
            for (int i = 0; i < TM; i++)
#pragma unroll
                for (int j = 0; j < TN; j++)
                    acc[i][j] = fmaf(a[i], b[j], acc[i][j]);
        }
    }

    // --- epilogue: bias + tanh ---
#pragma unroll
    for (int i = 0; i < TM; i++) {
        int grow = bm + trow * TM + i;
        if (grow >= M) continue;
        const float* brow = bias + (size_t)grow * D + bn + tcol * TN;
        float* crow = C + (size_t)grow * D + bn + tcol * TN;
        float4 o1, o2;
        o1.x = tanhf(acc[i][0] + brow[0]);
        o1.y = tanhf(acc[i][1] + brow[1]);
        o1.z = tanhf(acc[i][2] + brow[2]);
        o1.w = tanhf(acc[i][3] + brow[3]);
        o2.x = tanhf(acc[i][4] + brow[4]);
        o2.y = tanhf(acc[i][5] + brow[5]);
        o2.z = tanhf(acc[i][6] + brow[6]);
        o2.w = tanhf(acc[i][7] + brow[7]);
        *(float4*)(crow)     = o1;
        *(float4*)(crow + 4) = o2;
    }
}

// ---------------- launcher ----------------
extern "C" void kernel_launch(void* const* d_in, const int* in_sizes, int n_in,
                              void* d_out, int out_size) {
    const float* vectors = (const float*)d_in[0];
    const float* Wl = (const float*)d_in[1];
    const float* Wr = (const float*)d_in[2];
    float* out = (float*)d_out;

    float *bufA, *bufB, *u, *WT;
    cudaGetSymbolAddress((void**)&bufA, g_bufA);
    cudaGetSymbolAddress((void**)&bufB, g_bufB);
    cudaGetSymbolAddress((void**)&u, g_u);
    cudaGetSymbolAddress((void**)&WT, g_WT);

    // Build WT once per call (deterministic, cheap).
    prep_wt_kernel<<<(K2 * D + 255) / 256, 256>>>(Wl, Wr, WT);

    // offsets[l] = (4^l - 1) / 3
    static const int offs[9] = {0, 1, 5, 21, 85, 341, 1365, 5461, 21845};

    const float* h_in = vectors + (size_t)offs[8] * D;   // leaves: 65536 x 256
    for (int l = 7; l >= 0; --l) {
        int n_par = 1 << (2 * l);

        int total4 = n_par * 128;
        reduce_kernel<<<(total4 + 255) / 256, 256>>>(h_in, u, n_par);

        float* outp = (l == 0) ? out : ((l & 1) ? bufA : bufB);
        const float* bias = vectors + (size_t)offs[l] * D;

        dim3 grid(D / BN, (n_par + BM - 1) / BM);
        gemm_tanh_kernel<<<grid, 128>>>(u, WT, bias, outp, n_par);

        h_in = outp;
    }
}

// round 3
// speedup vs baseline: 1.5997x; 1.5997x over previous
#include <cuda_runtime.h>
#include <cuda_bf16.h>
#include <cstdint>
#include <math.h>

// CBTree B=4, L=9, d=256.
// Per level: u[p] (512 fp32) = child combine; h_out[p,n] = tanh(u . W(n,:) + bias[p,n])
// Split-bf16: Acat=[hi(u)|lo(u)|hi(u)] (K=1536), Bcat=[hi(W)|hi(W)|lo(W)] (per n row)
// C = Acat . Bcat^T = hi*hi + lo*hi + hi*lo  (~16-bit mantissa, fp32 accumulate)

#define D 256
#define KU 512
#define KCAT 1536
#define ROWB 3072         // bytes per Acat/Bcat row
#define BK 64             // k per stage (128 B per row)
#define NIT (KCAT / BK)   // 24
#define SROW 144          // smem row stride bytes (128 data + 16 pad, conflict-free)
#define STAGE_BYTES (128 * SROW)          // 18432 per operand tile
#define SMEM_TOTAL (4 * STAGE_BYTES)      // A0,B0,A1,B1 = 73728

// ---------------- static device scratch ----------------
__device__ float g_hA[16384 * 256];
__device__ float g_hB[16384 * 256];
__device__ __nv_bfloat16 g_Acat[16384 * 1536];   // 48 MB
__device__ __nv_bfloat16 g_Bcat[256 * 1536];     // 768 KB

// ---------------- helpers ----------------
__device__ __forceinline__ uint32_t smem_u32(const void* p) {
    uint32_t a;
    asm("{ .reg .u64 t; cvta.to.shared.u64 t, %1; cvt.u32.u64 %0, t; }" : "=r"(a) : "l"(p));
    return a;
}
__device__ __forceinline__ void cp_async16(uint32_t dst, const void* src, bool pred) {
    int sz = pred ? 16 : 0;
    asm volatile("cp.async.cg.shared.global [%0], [%1], 16, %2;"
                 :: "r"(dst), "l"(src), "r"(sz));
}
#define CP_COMMIT() asm volatile("cp.async.commit_group;" ::: "memory")

__device__ __forceinline__ void ldm_x4(uint32_t* r, uint32_t addr) {
    asm volatile("ldmatrix.sync.aligned.m8n8.x4.shared.b16 {%0,%1,%2,%3}, [%4];"
                 : "=r"(r[0]), "=r"(r[1]), "=r"(r[2]), "=r"(r[3]) : "r"(addr));
}
__device__ __forceinline__ void mma_bf16(float* c, const uint32_t* a, uint32_t b0, uint32_t b1) {
    asm volatile("mma.sync.aligned.m16n8k16.row.col.f32.bf16.bf16.f32 "
                 "{%0,%1,%2,%3}, {%4,%5,%6,%7}, {%8,%9}, {%0,%1,%2,%3};"
                 : "+f"(c[0]), "+f"(c[1]), "+f"(c[2]), "+f"(c[3])
                 : "r"(a[0]), "r"(a[1]), "r"(a[2]), "r"(a[3]), "r"(b0), "r"(b1));
}

// ---------------- prep: Bcat from Wl/Wr ----------------
__global__ void prep_w_kernel(const float* __restrict__ Wl,
                              const float* __restrict__ Wr,
                              __nv_bfloat16* __restrict__ Bcat) {
    int idx = blockIdx.x * blockDim.x + threadIdx.x;   // 256*512
    if (idx >= D * KU) return;
    int n = idx >> 9;
    int k = idx & 511;
    float w = (k < D) ? Wl[n * D + k] : Wr[n * D + (k - D)];
    __nv_bfloat16 hi = __float2bfloat16_rn(w);
    __nv_bfloat16 lo = __float2bfloat16_rn(w - __bfloat162float(hi));
    Bcat[(size_t)n * KCAT + k] = hi;
    Bcat[(size_t)n * KCAT + 512 + k] = hi;
    Bcat[(size_t)n * KCAT + 1024 + k] = lo;
}

// ---------------- reduce + split: h (4*n_par x 256 fp32) -> Acat (n_par x 1536 bf16) ----------------
__global__ void reduce_split_kernel(const float* __restrict__ h,
                                    __nv_bfloat16* __restrict__ Acat,
                                    int n_par) {
    int idx = blockIdx.x * blockDim.x + threadIdx.x;   // n_par * 512
    if (idx >= n_par * KU) return;
    int p = idx >> 9;
    int k = idx & 511;
    const float* hp = h + (size_t)p * 1024;
    float u;
    if (k < D) {
        u = hp[k] + (2.0f / 3.0f) * hp[D + k] + (1.0f / 3.0f) * hp[2 * D + k];
    } else {
        int j = k - D;
        u = (1.0f / 3.0f) * hp[D + j] + (2.0f / 3.0f) * hp[2 * D + j] + hp[3 * D + j];
    }
    __nv_bfloat16 hi = __float2bfloat16_rn(u);
    __nv_bfloat16 lo = __float2bfloat16_rn(u - __bfloat162float(hi));
    __nv_bfloat16* row = Acat + (size_t)p * KCAT;
    row[k] = hi;
    row[512 + k] = lo;
    row[1024 + k] = hi;
}

// ---------------- mma.sync GEMM + bias + tanh ----------------
// CTA: 128(M) x 128(N). 8 warps as 4(m) x 2(n): warp tile 32 x 64.
// K = 1536 in 24 stages of 64, cp.async double buffered.
__global__ void __launch_bounds__(256)
gemm_mma_kernel(const __nv_bfloat16* __restrict__ A,
                const __nv_bfloat16* __restrict__ B,
                const float* __restrict__ bias,
                float* __restrict__ C, int M) {
    extern __shared__ __align__(128) char smem[];
    const uint32_t sbase = smem_u32(smem);
    const int tid = threadIdx.x;
    const int wid = tid >> 5;
    const int lid = tid & 31;
    const int bm = blockIdx.y * 128;
    const int bn = blockIdx.x * 128;

    const char* Ab = (const char*)A;
    const char* Bb = (const char*)B;

    // ---- stage loader ----
    auto load_stage = [&](int buf, int kb) {
        uint32_t sA = sbase + buf * 2 * STAGE_BYTES;
        uint32_t sB = sA + STAGE_BYTES;
#pragma unroll
        for (int i = 0; i < 4; i++) {
            int id = i * 256 + tid;
            int r = id >> 3, c = id & 7;
            bool p = (bm + r) < M;
            const char* src = Ab + (size_t)(bm + r) * ROWB + kb * 128 + c * 16;
            if (!p) src = Ab;
            cp_async16(sA + r * SROW + c * 16, src, p);
        }
#pragma unroll
        for (int i = 0; i < 4; i++) {
            int id = i * 256 + tid;
            int r = id >> 3, c = id & 7;
            const char* src = Bb + (size_t)(bn + r) * ROWB + kb * 128 + c * 16;
            cp_async16(sB + r * SROW + c * 16, src, true);
        }
        CP_COMMIT();
    };

    float acc[2][8][4];
#pragma unroll
    for (int mf = 0; mf < 2; mf++)
#pragma unroll
        for (int nf = 0; nf < 8; nf++)
#pragma unroll
            for (int q = 0; q < 4; q++) acc[mf][nf][q] = 0.0f;

    const int wm = (wid & 3) * 32;
    const int wn = (wid >> 2) * 64;
    // ldmatrix lane address offsets (within a stage buffer)
    const uint32_t aOff = (uint32_t)(wm + (lid & 7) + ((lid & 8) ? 8 : 0)) * SROW +
                          ((lid & 16) ? 16 : 0);
    const uint32_t bOff = (uint32_t)(wn + (lid & 7) + ((lid & 16) ? 8 : 0)) * SROW +
                          ((lid & 8) ? 16 : 0);

    load_stage(0, 0);
    load_stage(1, 1);

    for (int it = 0; it < NIT; it++) {
        if (it + 2 < NIT) {
            asm volatile("cp.async.wait_group 1;" ::: "memory");
        } else {
            asm volatile("cp.async.wait_group 0;" ::: "memory");
        }
        __syncthreads();

        int buf = it & 1;
        uint32_t sA = sbase + buf * 2 * STAGE_BYTES;
        uint32_t sB = sA + STAGE_BYTES;
        uint32_t aAddr = sA + aOff;
        uint32_t bAddr = sB + bOff;

#pragma unroll
        for (int kk = 0; kk < 4; kk++) {
            uint32_t a0[4], a1[4];
            ldm_x4(a0, aAddr + kk * 32);
            ldm_x4(a1, aAddr + 16 * SROW + kk * 32);
            uint32_t bb[4][4];
#pragma unroll
            for (int nf2 = 0; nf2 < 4; nf2++)
                ldm_x4(bb[nf2], bAddr + nf2 * 16 * SROW + kk * 32);
#pragma unroll
            for (int nf2 = 0; nf2 < 4; nf2++) {
                mma_bf16(acc[0][nf2 * 2 + 0], a0, bb[nf2][0], bb[nf2][1]);
                mma_bf16(acc[0][nf2 * 2 + 1], a0, bb[nf2][2], bb[nf2][3]);
                mma_bf16(acc[1][nf2 * 2 + 0], a1, bb[nf2][0], bb[nf2][1]);
                mma_bf16(acc[1][nf2 * 2 + 1], a1, bb[nf2][2], bb[nf2][3]);
            }
        }
        __syncthreads();
        if (it + 2 < NIT) load_stage(buf, it + 2);
    }

    // ---- epilogue: bias + tanh ----
#pragma unroll
    for (int mf = 0; mf < 2; mf++) {
#pragma unroll
        for (int half = 0; half < 2; half++) {
            int grow = bm + wm + mf * 16 + (lid >> 2) + half * 8;
            if (grow >= M) continue;
            const float* brow = bias + (size_t)grow * D + bn + wn;
            float* crow = C + (size_t)grow * D + bn + wn;
#pragma unroll
            for (int nf = 0; nf < 8; nf++) {
                int col = nf * 8 + 2 * (lid & 3);
                float2 bv = *(const float2*)(brow + col);
                float2 o;
                o.x = tanhf(acc[mf][nf][half * 2 + 0] + bv.x);
                o.y = tanhf(acc[mf][nf][half * 2 + 1] + bv.y);
                *(float2*)(crow + col) = o;
            }
        }
    }
}

// ---------------- launcher ----------------
extern "C" void kernel_launch(void* const* d_in, const int* in_sizes, int n_in,
                              void* d_out, int out_size) {
    const float* vectors = (const float*)d_in[0];
    const float* Wl = (const float*)d_in[1];
    const float* Wr = (const float*)d_in[2];
    float* out = (float*)d_out;

    float *hA, *hB;
    __nv_bfloat16 *Acat, *Bcat;
    cudaGetSymbolAddress((void**)&hA, g_hA);
    cudaGetSymbolAddress((void**)&hB, g_hB);
    cudaGetSymbolAddress((void**)&Acat, g_Acat);
    cudaGetSymbolAddress((void**)&Bcat, g_Bcat);

    cudaFuncSetAttribute(gemm_mma_kernel,
                         cudaFuncAttributeMaxDynamicSharedMemorySize, SMEM_TOTAL);

    prep_w_kernel<<<(D * KU + 255) / 256, 256>>>(Wl, Wr, Bcat);

    static const int offs[9] = {0, 1, 5, 21, 85, 341, 1365, 5461, 21845};

    const float* h_in = vectors + (size_t)offs[8] * D;   // leaves 65536 x 256
    for (int l = 7; l >= 0; --l) {
        int n_par = 1 << (2 * l);

        int total = n_par * KU;
        reduce_split_kernel<<<(total + 255) / 256, 256>>>(h_in, Acat, n_par);

        float* outp = (l == 0) ? out : ((l & 1) ? hA : hB);
        const float* bias = vectors + (size_t)offs[l] * D;

        dim3 grid(2, (n_par + 127) / 128);
        gemm_mma_kernel<<<grid, 256, SMEM_TOTAL>>>(Acat, Bcat, bias, outp, n_par);

        h_in = outp;
    }
}